// round 13
// baseline (speedup 1.0000x reference)
#include <cuda_runtime.h>

#define NB 64
#define NN 1024
#define NWORDS 32          // NN/32 bitmask words per node row
#define NITER 5

// scratch (no allocations allowed)
__device__ float    g_feats[NB * NN];  // per-graph label histograms (6 stages)
__device__ float    g_dnorm[NB];       // sqrt(dot(feats_b, feats_b))
__device__ unsigned g_bar;             // monotonic grid-barrier ticket counter

// compare-exchange
__device__ __forceinline__ unsigned cex(unsigned a, unsigned b, bool keep_min)
{
    unsigned mn = a < b ? a : b;
    unsigned mx = a < b ? b : a;
    return keep_min ? mn : mx;
}

__device__ __forceinline__ unsigned stage_single(const unsigned* in, int t, int k, int j)
{
    bool asc = ((t & k) == 0);
    return cex(in[t], in[t ^ j], (((t & j) == 0) == asc));
}

// two consecutive stages (j1 then j2=j1/2) fused: 4 reads, 3 cex.
__device__ __forceinline__ unsigned stage_pair(const unsigned* in, int t, int k, int j1, int j2)
{
    bool asc = ((t & k) == 0);
    bool km1 = (((t & j1) == 0) == asc);
    unsigned a  = cex(in[t],      in[t ^ j1],        km1);
    unsigned bb = cex(in[t ^ j2], in[(t ^ j2) ^ j1], km1);
    return cex(a, bb, (((t & j2) == 0) == asc));
}

// intra-warp bitonic merge on 32-bit keys: j = jstart..1 via shuffles
__device__ __forceinline__ unsigned warp_merge32(unsigned v, int t, int k, int jstart)
{
    bool dir = ((t & k) == 0);
    #pragma unroll
    for (int j = jstart; j > 0; j >>= 1) {
        unsigned o = __shfl_xor_sync(0xffffffffu, v, j);
        bool keep_min = (((t & j) == 0) == dir);
        unsigned mn = v < o ? v : o;
        unsigned mx = v < o ? o : v;
        v = keep_min ? mn : mx;
    }
    return v;
}

// -------------------------------------------------------------------------
// FUSED kernel: one block per graph; 64 blocks (all co-resident: 1 CTA/SM,
// 64 < 148 SMs, single wave -> global spin barrier is deadlock-free).
// Phase 1: WL iterations -> feats + dnorm.
// Grid barrier (monotonic ticket; graph-replay safe).
// Phase 2: normalized Gram row b (64 dots, 2 per warp, L2-resident reads).
// Dynamic SMEM (217088 B, opt-in):
//   [0      , 131072) : unsigned smask[32768]   adjacency bits
//   [131072 , 196608) : u16 s_ent[32768]        CSR entries (even-aligned runs)
//   [196608 , 200704) : int s_lab[1024]         labels
//   [200704 , 204800) : int s_cnt[1024]         histogram counts
//   [204800 , 208896) : unsigned s_keyA[1024]   sort ping buffer (gram: sf)
//   [208896 , 212992) : unsigned s_keyB[1024]   sort pong buffer (run-pos)
//   [212992 , 217088) : int s_scan[1024]        rank per sorted position
// -------------------------------------------------------------------------
extern "C" __global__ void __launch_bounds__(1024, 1)
wl_fused_kernel(const int* __restrict__ esrc, const int* __restrict__ edst,
                const int* __restrict__ labels0, const float* __restrict__ hw,
                int E, float* __restrict__ out)
{
    extern __shared__ unsigned char s_raw[];
    unsigned*       smask  = (unsigned*)s_raw;                  // 128KB
    unsigned short* s_ent  = (unsigned short*)(s_raw + 131072); // 64KB
    int*            s_lab  = (int*)(s_raw + 196608);            // 4KB
    int*            s_cnt  = (int*)(s_raw + 200704);            // 4KB
    unsigned*       s_keyA = (unsigned*)(s_raw + 204800);       // 4KB
    unsigned*       s_keyB = (unsigned*)(s_raw + 208896);       // 4KB
    int*            s_scan = (int*)(s_raw + 212992);            // 4KB
    __shared__ int s_warp[32];

    const int t    = threadIdx.x;
    const int b    = blockIdx.x;
    const int lane = t & 31;
    const int wid  = t >> 5;
    const float w0 = hw[0], w1 = hw[1];

    // --- zero mask + counts ---
    #pragma unroll
    for (int w = 0; w < NWORDS; w++) smask[t + w * 1024] = 0u;
    s_cnt[t] = 0;
    __syncthreads();

    // --- build directed adjacency bitmask (atomicOr dedupes edges) ---
    if ((E & 3) == 0) {
        const int4* s4 = (const int4*)(esrc + (size_t)b * E);
        const int4* d4 = (const int4*)(edst + (size_t)b * E);
        const int n4 = E >> 2;
        for (int i = t; i < n4; i += 1024) {
            int4 s = s4[i];
            int4 d = d4[i];
            atomicOr(&smask[(s.x << 5) + (d.x >> 5)], 1u << (d.x & 31));
            atomicOr(&smask[(s.y << 5) + (d.y >> 5)], 1u << (d.y & 31));
            atomicOr(&smask[(s.z << 5) + (d.z >> 5)], 1u << (d.z & 31));
            atomicOr(&smask[(s.w << 5) + (d.w >> 5)], 1u << (d.w & 31));
        }
    } else {
        for (int e = t; e < E; e += 1024) {
            int s = esrc[b * E + e];
            int d = edst[b * E + e];
            atomicOr(&smask[(s << 5) + (d >> 5)], 1u << (d & 31));
        }
    }

    // --- initial labels + stage-0 histogram (warp-aggregated atomics) ---
    int mylab = labels0[b * NN + t];
    s_lab[t] = mylab;
    {
        unsigned peers = __match_any_sync(0xffffffffu, mylab);
        int leader = __ffs(peers) - 1;
        int cnt    = __popc(peers);
        if (lane == leader) atomicAdd(&s_cnt[mylab], cnt);
    }
    __syncthreads();

    // --- degree (staggered word order -> conflict-free LDS) ---
    int deg = 0;
    #pragma unroll
    for (int wi = 0; wi < NWORDS; wi++) {
        int w = (wi + t) & 31;
        deg += __popc(smask[(t << 5) + w]);
    }
    const int degPad = (deg + 1) & ~1;     // even-align each node's CSR run

    // --- K = max degree, exclusive scan of degPad -> even CSR offsets ---
    int kv = deg;
    #pragma unroll
    for (int o = 16; o > 0; o >>= 1) kv = max(kv, __shfl_xor_sync(0xffffffffu, kv, o));
    int incl = degPad;
    #pragma unroll
    for (int o = 1; o < 32; o <<= 1) {
        int n = __shfl_up_sync(0xffffffffu, incl, o);
        if (lane >= o) incl += n;
    }
    if (lane == 31) { s_warp[wid] = incl; s_scan[wid] = kv; }
    __syncthreads();
    int wpre, K;
    {
        int x = s_warp[lane];
        int xm = (lane < wid) ? x : 0;
        #pragma unroll
        for (int o = 16; o > 0; o >>= 1) xm += __shfl_xor_sync(0xffffffffu, xm, o);
        wpre = xm;
        int m = s_scan[lane & 31];
        #pragma unroll
        for (int o = 16; o > 0; o >>= 1) m = max(m, __shfl_xor_sync(0xffffffffu, m, o));
        K = m;
    }
    const int off = wpre + incl - degPad;  // even exclusive offset
    __syncthreads();

    // --- build CSR u16 neighbor entries (once) ---
    {
        int p = off;
        #pragma unroll
        for (int w = 0; w < NWORDS; w++) {
            unsigned m = smask[(t << 5) + w];
            int base = w << 5;
            while (m) {
                int bb = __ffs(m) - 1;
                m &= m - 1;
                s_ent[p++] = (unsigned short)(base + bb);
            }
        }
    }
    __syncthreads();

    const float Kw0 = __fmul_rn((float)K, w0);
    const unsigned* e32base = (const unsigned*)s_ent;

    for (int it = 0; it < NITER; it++) {
        // --- seg = sum of neighbor labels; u32-packed reads ---
        int seg = 0;
        {
            const unsigned* e32 = e32base + (off >> 1);
            const int nf = deg >> 1;
            #pragma unroll 4
            for (int n = 0; n < nf; n++) {
                unsigned e = e32[n];
                seg += s_lab[e & 0xFFFFu] + s_lab[e >> 16];
            }
            if (deg & 1) seg += s_lab[s_ent[off + deg - 1]];
        }

        // --- hashed = (K*w0)*lab + w1*(seg+deg-K), no FMA contraction ---
        float h = __fadd_rn(__fmul_rn(Kw0, (float)mylab),
                            __fmul_rn(w1, (float)(seg + deg - K)));
        h = __fadd_rn(h, 0.0f);               // canonicalize -0 -> +0
        unsigned u = __float_as_uint(h);
        u = (u & 0x80000000u) ? ~u : (u | 0x80000000u);   // order-preserving map
        const unsigned mykey = u;
        unsigned v = u;

        // --- warp phase: k = 2..32 in registers ---
        #pragma unroll
        for (int k = 2; k <= 32; k <<= 1)
            v = warp_merge32(v, t, k, k >> 1);

        unsigned* cur = s_keyA;
        unsigned* nxt = s_keyB;
        cur[t] = v;
        __syncthreads();

        // --- k=64 ---
        v = stage_single(cur, t, 64, 32);
        v = warp_merge32(v, t, 64, 16);
        nxt[t] = v; { unsigned* tmp = cur; cur = nxt; nxt = tmp; }
        __syncthreads();

        // --- k=128 ---
        v = stage_pair(cur, t, 128, 64, 32);
        v = warp_merge32(v, t, 128, 16);
        nxt[t] = v; { unsigned* tmp = cur; cur = nxt; nxt = tmp; }
        __syncthreads();

        // --- k=256 ---
        v = stage_pair(cur, t, 256, 128, 64);
        nxt[t] = v; { unsigned* tmp = cur; cur = nxt; nxt = tmp; }
        __syncthreads();
        v = stage_single(cur, t, 256, 32);
        v = warp_merge32(v, t, 256, 16);
        nxt[t] = v; { unsigned* tmp = cur; cur = nxt; nxt = tmp; }
        __syncthreads();

        // --- k=512 ---
        v = stage_pair(cur, t, 512, 256, 128);
        nxt[t] = v; { unsigned* tmp = cur; cur = nxt; nxt = tmp; }
        __syncthreads();
        v = stage_pair(cur, t, 512, 64, 32);
        v = warp_merge32(v, t, 512, 16);
        nxt[t] = v; { unsigned* tmp = cur; cur = nxt; nxt = tmp; }
        __syncthreads();

        // --- k=1024 ---
        v = stage_pair(cur, t, 1024, 512, 256);
        nxt[t] = v; { unsigned* tmp = cur; cur = nxt; nxt = tmp; }
        __syncthreads();
        v = stage_pair(cur, t, 1024, 128, 64);
        nxt[t] = v; { unsigned* tmp = cur; cur = nxt; nxt = tmp; }
        __syncthreads();
        v = stage_single(cur, t, 1024, 32);
        v = warp_merge32(v, t, 1024, 16);
        nxt[t] = v; { unsigned* tmp = cur; cur = nxt; nxt = tmp; }
        __syncthreads();
        // cur[] fully sorted; nxt[] stale keys (reused as s_pos); v = cur[t]

        // --- tail section 1: flags, warp scan, broadcast prefix, scatter ---
        int flag = 0;
        if (t > 0) flag = (v != cur[t - 1]) ? 1 : 0;
        int val = flag;
        #pragma unroll
        for (int o = 1; o < 32; o <<= 1) {
            int n = __shfl_up_sync(0xffffffffu, val, o);
            if (lane >= o) val += n;
        }
        if (lane == 31) s_warp[wid] = val;
        __syncthreads();

        int wp = s_warp[lane];
        wp = (lane < wid) ? wp : 0;
        #pragma unroll
        for (int o = 16; o > 0; o >>= 1) wp += __shfl_xor_sync(0xffffffffu, wp, o);
        const int rank_p = val + wp;
        int* s_pos = (int*)nxt;
        s_scan[t] = rank_p;
        const bool isstart = (t == 0) | (flag != 0);
        if (isstart) s_pos[rank_p] = t;
        __syncthreads();

        // --- tail section 2: run-length histogram + label update ---
        if (isstart) {
            const int R = s_scan[1023];          // max rank this iteration
            int end = (rank_p == R) ? 1024 : s_pos[rank_p + 1];
            s_cnt[rank_p] += end - t;
        }
        if (it < NITER - 1) {
            int lo = 0;
            #pragma unroll
            for (int s = 512; s > 0; s >>= 1)
                if (cur[lo + s - 1] < mykey) lo += s;
            int rank = s_scan[lo];
            s_lab[t] = rank;
            mylab    = rank;
        }
        __syncthreads();
    }

    // --- feats (global + smem copy for gram) + norm ---
    float c = (float)s_cnt[t];
    float* sf = (float*)s_keyA;            // free after final iteration barrier
    sf[t] = c;
    g_feats[b * NN + t] = c;

    float sq = c * c;
    #pragma unroll
    for (int o = 16; o > 0; o >>= 1) sq += __shfl_xor_sync(0xffffffffu, sq, o);
    if (lane == 0) s_warp[wid] = __float_as_int(sq);
    __syncthreads();
    if (t < 32) {
        float x = __int_as_float(s_warp[t]);
        #pragma unroll
        for (int o = 16; o > 0; o >>= 1) x += __shfl_xor_sync(0xffffffffu, x, o);
        if (t == 0) g_dnorm[b] = sqrtf(x);
    }

    // --- grid barrier (monotonic ticket: graph-replay safe) ---
    __threadfence();                       // publish g_feats/g_dnorm to L2
    __syncthreads();
    if (t == 0) {
        unsigned ticket = atomicAdd(&g_bar, 1u);
        unsigned target = (ticket / NB + 1u) * NB;
        while (*(volatile unsigned*)&g_bar < target) { }
    }
    __syncthreads();
    __threadfence();

    // --- Phase 2: normalized Gram row b; 2 dots per warp from L2 ---
    const float dn_b = g_dnorm[b];
    const float4* sf4 = (const float4*)sf;
    for (int jj = wid; jj < NB; jj += 32) {
        const float4* fj4 = (const float4*)&g_feats[jj * NN];
        float s = 0.0f;
        #pragma unroll
        for (int k = lane; k < NN / 4; k += 32) {
            float4 a  = sf4[k];
            float4 cc = fj4[k];
            s += a.x * cc.x + a.y * cc.y + a.z * cc.z + a.w * cc.w;
        }
        #pragma unroll
        for (int o = 16; o > 0; o >>= 1) s += __shfl_xor_sync(0xffffffffu, s, o);
        if (lane == 0) out[b * NB + jj] = s / (dn_b * g_dnorm[jj]);
    }
}

extern "C" void kernel_launch(void* const* d_in, const int* in_sizes, int n_in,
                              void* d_out, int out_size)
{
    const int*   esrc = (const int*)d_in[0];
    const int*   edst = (const int*)d_in[1];
    const int*   lab  = (const int*)d_in[2];
    const float* hw   = (const float*)d_in[3];
    const int E = in_sizes[0] / NB;

    const size_t smem_wl = 217088;  // 128K mask + 64K ent + 5x4K arrays
    static bool attr_done = false;
    if (!attr_done) {
        cudaFuncSetAttribute(wl_fused_kernel,
                             cudaFuncAttributeMaxDynamicSharedMemorySize,
                             (int)smem_wl);
        attr_done = true;
    }
    wl_fused_kernel<<<NB, 1024, smem_wl>>>(esrc, edst, lab, hw, E, (float*)d_out);
}